// round 9
// baseline (speedup 1.0000x reference)
#include <cuda_runtime.h>
#include <math.h>
#include <stdint.h>

#define Bn 32
#define Nn 262144
#define Gn 256
#define SEGSZ 2048              // elements per warp-segment
#define SEGPB (Nn / SEGSZ)      // 128 segments per batch
#define NSEG (Bn * SEGPB)       // 4096 segments
#define NWARP 8                 // warps per block (sortlocal)
#define CHUNK 16384
#define NBLK ((Bn * Nn) / CHUNK)   // 512

// ---------------- scratch (device globals; no allocation) ----------------
__device__ unsigned g_loff[NSEG][Gn];  // per-segment exclusive group prefix
__device__ unsigned g_tot[Bn][Gn];     // group totals (written by k_fold)
__device__ float    g_local[Bn * Nn];  // per-segment group-sorted values
__device__ float4   g_SMM[Bn * Gn];    // per-group (sum, min, max, -)
__device__ float4   g_P[Bn * Gn];      // per-group (mn', rng, df, f0')

__device__ __forceinline__ bool bit_isnan(float f) {
    return (__float_as_uint(f) << 1) > 0xFF000000u;
}
__device__ __forceinline__ bool bit_iszero(float f) {
    return (__float_as_uint(f) << 1) == 0u;
}
__device__ __forceinline__ bool bit_nonfinite(float f) {
    return (__float_as_uint(f) << 1) >= 0xFF000000u;
}

// ---------------- kernel 1: fused count+rank+local-place -----------------
// smem per warp: s_h (1KB: counts -> loff) + s_packed (8KB: g | rank<<8)
#define SORT_SMEM (NWARP * Gn * 4 + NWARP * SEGSZ * 4)   // 72KB

__global__ __launch_bounds__(256) void k_sortlocal(const float* __restrict__ pr,
                                                   const int* __restrict__ vr) {
    extern __shared__ unsigned char sm[];
    int t = threadIdx.x, w = t >> 5, l = t & 31;
    unsigned lt = (1u << l) - 1u;

    unsigned* s_h      = (unsigned*)sm + w * Gn;                    // counts -> loff
    unsigned* s_packed = (unsigned*)(sm + NWARP * Gn * 4) + w * SEGSZ;

    long seg = (long)blockIdx.x * NWARP + w;

#pragma unroll
    for (int i = l; i < Gn; i += 32) s_h[i] = 0u;
    __syncwarp();

    const int* __restrict__ vs = vr + seg * SEGSZ;

    // ---- pass 1: count + stable rank in the same match pass ----
    // idx = r*32 + l is strictly n-ordered across rounds and lanes, so
    // rank = (count of g so far) + (lane rank among this round's matches)
    // is the exact stable within-segment rank.
#pragma unroll 4
    for (int r = 0; r < SEGSZ / 32; ++r) {
        int g = vs[r * 32 + l];
        unsigned m = __match_any_sync(0xFFFFFFFFu, g);
        unsigned lr = __popc(m & lt);
        unsigned cur = s_h[g];          // broadcast within matched subset
        __syncwarp();
        s_packed[r * 32 + l] = (unsigned)g | ((cur + lr) << 8);
        if (lr == 0u) s_h[g] = cur + __popc(m);
        __syncwarp();
    }

    // ---- scan: counts -> exclusive local offsets; write g_loff row ----
    unsigned c[8], loffreg[8];
#pragma unroll
    for (int k = 0; k < 8; ++k) c[k] = s_h[l * 8 + k];
    unsigned lsum = 0;
#pragma unroll
    for (int k = 0; k < 8; ++k) lsum += c[k];
    unsigned sc = lsum;
#pragma unroll
    for (int d = 1; d < 32; d <<= 1) {
        unsigned v = __shfl_up_sync(0xFFFFFFFFu, sc, d);
        if (l >= d) sc += v;
    }
    unsigned running = sc - lsum;       // exclusive over lanes
#pragma unroll
    for (int k = 0; k < 8; ++k) {
        loffreg[k] = running;
        running += c[k];
    }
    __syncwarp();
#pragma unroll
    for (int k = 0; k < 8; ++k) s_h[l * 8 + k] = loffreg[k];   // s_h now = loff
    ((uint4*)g_loff[seg])[l * 2]     = make_uint4(loffreg[0], loffreg[1], loffreg[2], loffreg[3]);
    ((uint4*)g_loff[seg])[l * 2 + 1] = make_uint4(loffreg[4], loffreg[5], loffreg[6], loffreg[7]);
    __syncwarp();

    // ---- pass 2: place values (scattered STG within this segment's 8KB) ----
    const float* __restrict__ ps = pr + seg * SEGSZ;
    float* __restrict__ dst = g_local + seg * SEGSZ;
#pragma unroll 4
    for (int r = 0; r < SEGSZ / 32; ++r) {
        unsigned pk = s_packed[r * 32 + l];
        float p = ps[r * 32 + l];
        unsigned g = pk & 255u;
        unsigned slot = s_h[g] + (pk >> 8);
        dst[slot] = p;
    }
}

// ---------------- kernel 2: sequential fold over per-segment runs --------
__global__ __launch_bounds__(32) void k_fold() {
    int gid = blockIdx.x * 32 + threadIdx.x;   // 0..8191
    int b = gid >> 8, g = gid & 255;
    int segbase = b * SEGPB;

    float acc = 0.0f;
    float mn =  __int_as_float(0x7F800000);    // +inf
    float mx = -__int_as_float(0x7F800000);    // -inf
    unsigned tot = 0;

    // prefetch offsets for segment 0
    unsigned off_c = g_loff[segbase][g];
    unsigned nxt_c = (g < 255) ? g_loff[segbase][g + 1] : (unsigned)SEGSZ;

    for (int s = 0; s < SEGPB; ++s) {
        unsigned off = off_c, nxt = nxt_c;
        if (s + 1 < SEGPB) {            // prefetch next segment's offsets
            off_c = g_loff[segbase + s + 1][g];
            nxt_c = (g < 255) ? g_loff[segbase + s + 1][g + 1] : (unsigned)SEGSZ;
        }
        unsigned cnt = nxt - off;
        tot += cnt;
        const float* __restrict__ dp = g_local + (long)(segbase + s) * SEGSZ + off;

        unsigned j = 0;
        for (; j + 8 <= cnt; j += 8) {
            float q0 = dp[j],     q1 = dp[j + 1], q2 = dp[j + 2], q3 = dp[j + 3];
            float q4 = dp[j + 4], q5 = dp[j + 5], q6 = dp[j + 6], q7 = dp[j + 7];
            acc = __fadd_rn(acc, q0);
            acc = __fadd_rn(acc, q1);
            acc = __fadd_rn(acc, q2);
            acc = __fadd_rn(acc, q3);
            acc = __fadd_rn(acc, q4);
            acc = __fadd_rn(acc, q5);
            acc = __fadd_rn(acc, q6);
            acc = __fadd_rn(acc, q7);
            mn = fminf(mn, fminf(fminf(fminf(q0, q1), fminf(q2, q3)),
                                 fminf(fminf(q4, q5), fminf(q6, q7))));
            mx = fmaxf(mx, fmaxf(fmaxf(fmaxf(q0, q1), fmaxf(q2, q3)),
                                 fmaxf(fmaxf(q4, q5), fmaxf(q6, q7))));
        }
        for (; j < cnt; ++j) {
            float a = dp[j];
            acc = __fadd_rn(acc, a);
            mn = fminf(mn, a); mx = fmaxf(mx, a);
        }
    }

    g_tot[b][g] = tot;
    g_SMM[gid] = make_float4(acc, mn, mx, 0.0f);
}

// ---------------- kernel 3: sort + per-group affine params ---------------
__global__ __launch_bounds__(Gn) void k_params(const float* __restrict__ inp_means,
                                               const float* __restrict__ W) {
    __shared__ float skey[Gn];
    __shared__ int   sid[Gn];
    __shared__ float f0u[Gn];
    __shared__ float f1u[Gn];

    int b = blockIdx.x;
    int g = threadIdx.x;
    int o = b * Gn + g;

    float4 smm = g_SMM[o];
    unsigned cnt = g_tot[b][g];
    bool any = (cnt > 0u);
    float vsum = any ? smm.x : 0.0f;
    float mn = smm.y, mx = smm.z;

    float W0 = W[0], W1 = W[1];
    float vmean = __fdiv_rn(__fadd_rn(__fmul_rn(inp_means[o], W0),
                                      __fmul_rn(vsum, W1)),
                            __fadd_rn(W0, W1));

    skey[g] = vmean;
    sid[g]  = g;
    __syncthreads();

    // bitonic sort on (value, id) == jax stable argsort
    for (int k = 2; k <= Gn; k <<= 1) {
        for (int j = k >> 1; j > 0; j >>= 1) {
            int ixj = g ^ j;
            if (ixj > g) {
                float a = skey[g], c = skey[ixj];
                int ia = sid[g], ic = sid[ixj];
                bool up = ((g & k) == 0);
                bool gt = (a > c) || (a == c && ia > ic);
                if (gt == up) {
                    skey[g] = c; skey[ixj] = a;
                    sid[g] = ic; sid[ixj] = ia;
                }
            }
            __syncthreads();
        }
    }

    float vsr   = skey[g];
    float vprev = (g == 0)      ? vsr : skey[g - 1];
    float vnext = (g == Gn - 1) ? __fmul_rn(vsr, 2.0f) : skey[g + 1];
    float f0 = __fdiv_rn(__fadd_rn(vprev, vsr), 1.999f);
    float f1 = __fdiv_rn(__fadd_rn(vsr, vnext), 2.001f);
    f0u[sid[g]] = f0;
    f1u[sid[g]] = f1;
    __syncthreads();

    bool ns = (mn == mx);   // empty group: inf == -inf -> false (matches ref)

    float mn2, mx2, f02, f12;
    if (!any) { mn2 = 0.0f; mx2 = 1.0f; f02 = 0.0f; f12 = 0.0f; }
    else {
        mn2 = ns ? 0.0f : mn;
        mx2 = ns ? 1.0f : mx;
        f02 = ns ? 0.0f : f0u[g];
        f12 = ns ? 1.0f : f1u[g];
    }
    float rng = __fsub_rn(mx2, mn2);
    float df  = __fsub_rn(f12, f02);
    g_P[o] = make_float4(mn2, rng, df, f02);
}

// ---------------- kernel 4: elementwise apply ----------------------------
// div #1 (t1/rng) stays exact (its bits feed error-amplified near-zero tmp);
// div #2 replaced by MUFU.RCP (uniform ~1e-7 relative, no amplification).
__device__ __forceinline__ float apply_one(float p, float4 P) {
    float t1  = __fsub_rn(p, P.x);
    float t2  = __fdiv_rn(t1, P.y);
    float t3  = __fmul_rn(t2, P.z);
    float tmp = __fadd_rn(t3, P.w);
    bool bad = bit_isnan(tmp) || bit_iszero(tmp);
    float den = bad ? 1.0f : tmp;
    float r;
    asm("rcp.approx.f32 %0, %1;" : "=f"(r) : "f"(den));
    float s = __fmul_rn(p, r);
    float scale = (bad || bit_nonfinite(s)) ? 0.0f : s;
    return __fmul_rn(p, scale);
}

__global__ __launch_bounds__(256) void k_apply(const float* __restrict__ pr,
                                               const int* __restrict__ vr,
                                               float* __restrict__ out) {
    __shared__ float4 sP[Gn];
    long base = (long)blockIdx.x * CHUNK;
    int b = blockIdx.x / (Nn / CHUNK);

    int t = threadIdx.x;
    sP[t] = g_P[b * Gn + t];
    __syncthreads();

    const float4* p4 = (const float4*)(pr + base);
    const int4*   v4 = (const int4*)(vr + base);
    float4*       o4 = (float4*)(out + base);

#pragma unroll 4
    for (int it = 0; it < CHUNK / 1024; ++it) {
        float4 p = p4[it * 256 + t];
        int4   v = v4[it * 256 + t];
        float4 r;
        r.x = apply_one(p.x, sP[v.x]);
        r.y = apply_one(p.y, sP[v.y]);
        r.z = apply_one(p.z, sP[v.z]);
        r.w = apply_one(p.w, sP[v.w]);
        o4[it * 256 + t] = r;
    }
}

// ---------------- launch --------------------------------------------------
extern "C" void kernel_launch(void* const* d_in, const int* in_sizes, int n_in,
                              void* d_out, int out_size) {
    const float* pr        = (const float*)d_in[0];
    const float* inp_means = (const float*)d_in[1];
    const int*   vr        = (const int*)d_in[2];
    const float* W         = (const float*)d_in[3];
    float* out = (float*)d_out;

    static int smem_set = 0;
    if (!smem_set) {
        cudaFuncSetAttribute(k_sortlocal, cudaFuncAttributeMaxDynamicSharedMemorySize,
                             SORT_SMEM);
        smem_set = 1;
    }

    k_sortlocal<<<NSEG / NWARP, 256, SORT_SMEM>>>(pr, vr);
    k_fold<<<(Bn * Gn) / 32, 32>>>();
    k_params<<<Bn, Gn>>>(inp_means, W);
    k_apply<<<NBLK, 256>>>(pr, vr, out);
}